// round 12
// baseline (speedup 1.0000x reference)
#include <cuda_runtime.h>
#include <math.h>
#include <stdint.h>

// TopKTokenChoiceRouter: logits = x(8192,4096) @ W(64,4096)^T ; softmax ; top-2.
// Output: [weights (T,2) fp32][indices (T,2) as fp32].
// mma.sync m16n8k8 tf32 (sm_80+ family-portable), 3-product tf32 emulation of fp32.
// tf32 conversion done with INTEGER rounding (no cvt.*.tf32 — suspected ptxas ICE).
// W pre-converted to fragment-ordered hi/lo scratch (L2-resident); x fragments
// loaded straight from global and split in registers. No smem, no barriers.

#define HS      4096
#define NEXP    64
#define TM      128            // tokens per CTA
#define NSPLIT  2
#define KPS     (HS / NSPLIT)  // 2048
#define NK8     (KPS / 8)      // 256 k8-steps per CTA
#define THREADS 256
#define TTOT    8192
#define GK8     (HS / 8)       // 512 global k8 steps

// W fragment scratch: [k8g][ntile(8)][reg(2)][lane(32)] of float2{hi,lo} = 2 MB
__device__ float2 g_wfrag[GK8 * 8 * 2 * 32];
__device__ float  g_partial[NSPLIT * TTOT * NEXP];     // 4 MB

// fp32 -> tf32 by integer RNE rounding to 10 mantissa bits. Low 13 bits zeroed,
// so hi is exactly representable and lo = v - hi is exact in fp32.
__device__ __forceinline__ uint32_t f32_to_tf32(float x) {
    uint32_t b = __float_as_uint(x);
    b += 0xFFFu + ((b >> 13) & 1u);
    return b & 0xFFFFE000u;
}

__device__ __forceinline__ void mma_tf32(float* c, const uint32_t* a, const uint32_t* b) {
    asm volatile(
        "mma.sync.aligned.m16n8k8.row.col.f32.tf32.tf32.f32 "
        "{%0,%1,%2,%3}, {%4,%5,%6,%7}, {%8,%9}, {%0,%1,%2,%3};"
        : "+f"(c[0]), "+f"(c[1]), "+f"(c[2]), "+f"(c[3])
        : "r"(a[0]), "r"(a[1]), "r"(a[2]), "r"(a[3]), "r"(b[0]), "r"(b[1]));
}

// ---------------- W pre-convert: fp32 -> tf32 hi/lo, fragment-ordered ----------------
__global__ void w_convert(const float* __restrict__ W)
{
    const int idx = blockIdx.x * 256 + threadIdx.x;   // 0 .. 64*4096-1
    const int n = idx >> 12;          // expert 0..63
    const int k = idx & 4095;
    const float v = W[idx];
    const uint32_t hb = f32_to_tf32(v);
    const float    hf = __uint_as_float(hb);
    const uint32_t lb = f32_to_tf32(v - hf);

    const int k8g = k >> 3;
    const int kin = k & 7;
    const int t   = kin & 3;
    const int reg = kin >> 2;
    const int nt  = n >> 3;
    const int lane = (n & 7) * 4 + t;   // B frag: col(n%8) = lane>>2, k%4 = lane&3
    g_wfrag[((k8g * 8 + nt) * 2 + reg) * 32 + lane] =
        make_float2(__uint_as_float(hb), __uint_as_float(lb));
}

// ---------------- GEMM partial kernel (mma.sync tf32) ----------------
__global__ __launch_bounds__(THREADS)
void router_gemm_mma(const float* __restrict__ x)
{
    const int tid  = threadIdx.x;
    const int w    = tid >> 5;          // warp 0..7
    const int lane = tid & 31;
    const int g    = lane >> 2;         // group 0..7
    const int t    = lane & 3;          // thread-in-group 0..3

    const int tok0  = blockIdx.x * TM;
    const int split = blockIdx.y;
    const int k8b   = split * (KPS / 8);   // global k8 base

    const int R0  = tok0 + (w >> 1) * 32;  // warp's first token row (M=32)
    const int ntb = (w & 1) * 4;           // warp's first n-tile (N=32)

    // A row pointers: mt in {0,1}, rows R0+mt*16+g and +8
    const float* xr[2][2];
#pragma unroll
    for (int mt = 0; mt < 2; mt++) {
        xr[mt][0] = x + (long)(R0 + mt * 16 + g) * HS + split * KPS + t;
        xr[mt][1] = xr[mt][0] + 8 * HS;
    }

    const float2* wf = g_wfrag + (long)(k8b * 8 + ntb) * 2 * 32 + lane;

    float acc[2][4][4];
#pragma unroll
    for (int mt = 0; mt < 2; mt++)
#pragma unroll
        for (int nt = 0; nt < 4; nt++)
#pragma unroll
            for (int c = 0; c < 4; c++) acc[mt][nt][c] = 0.0f;

#pragma unroll 4
    for (int k8 = 0; k8 < NK8; k8++) {
        const int ko = k8 * 8;

        // B fragments: 4 ntiles x 2 regs, hi/lo packed as float2
        uint32_t bh[4][2], bl[4][2];
#pragma unroll
        for (int nt = 0; nt < 4; nt++) {
#pragma unroll
            for (int reg = 0; reg < 2; reg++) {
                const float2 f = wf[((long)k8 * 8 + nt) * 2 * 32 + reg * 32];
                bh[nt][reg] = __float_as_uint(f.x);
                bl[nt][reg] = __float_as_uint(f.y);
            }
        }

        // A fragments per mtile: load fp32, split hi/lo in regs
#pragma unroll
        for (int mt = 0; mt < 2; mt++) {
            float av[4];
            av[0] = xr[mt][0][ko];       // (g,   t)
            av[1] = xr[mt][1][ko];       // (g+8, t)
            av[2] = xr[mt][0][ko + 4];   // (g,   t+4)
            av[3] = xr[mt][1][ko + 4];   // (g+8, t+4)

            uint32_t ah[4], al[4];
#pragma unroll
            for (int i = 0; i < 4; i++) {
                ah[i] = f32_to_tf32(av[i]);
                al[i] = f32_to_tf32(av[i] - __uint_as_float(ah[i]));
            }

#pragma unroll
            for (int nt = 0; nt < 4; nt++) {
                mma_tf32(acc[mt][nt], ah, bh[nt]);
                mma_tf32(acc[mt][nt], ah, bl[nt]);
                mma_tf32(acc[mt][nt], al, bh[nt]);
            }
        }
    }

    // ---- store partials: c0,c1 -> (row, 2t..2t+1), c2,c3 -> (row+8, ...) ----
    float* pb = g_partial + (long)split * TTOT * NEXP;
#pragma unroll
    for (int mt = 0; mt < 2; mt++) {
#pragma unroll
        for (int h = 0; h < 2; h++) {
            const int row = R0 + mt * 16 + g + 8 * h;
            float* dst = pb + (long)row * NEXP;
#pragma unroll
            for (int nt = 0; nt < 4; nt++)
                *(float2*)&dst[(ntb + nt) * 8 + 2 * t] =
                    make_float2(acc[mt][nt][2 * h], acc[mt][nt][2 * h + 1]);
        }
    }
}

// ---------------- reduce + softmax + top-2 ----------------
__global__ __launch_bounds__(256)
void router_reduce(float* __restrict__ out, int T)
{
    const int wid = threadIdx.x >> 5;
    const int l   = threadIdx.x & 31;
    const int t   = blockIdx.x * 8 + wid;
    if (t >= T) return;

    const float* p = g_partial + (long)t * NEXP + l;
    float v0 = 0.0f, v1 = 0.0f;
#pragma unroll
    for (int s = 0; s < NSPLIT; s++) {
        v0 += p[(long)s * TTOT * NEXP];
        v1 += p[(long)s * TTOT * NEXP + 32];
    }

    float m = fmaxf(v0, v1);
#pragma unroll
    for (int o = 16; o > 0; o >>= 1)
        m = fmaxf(m, __shfl_xor_sync(0xffffffffu, m, o));

    float se = __expf(v0 - m) + __expf(v1 - m);
#pragma unroll
    for (int o = 16; o > 0; o >>= 1)
        se += __shfl_xor_sync(0xffffffffu, se, o);

    float a1, a2; int i1, i2;
    if (v1 > v0) { a1 = v1; i1 = l + 32; a2 = v0; i2 = l; }
    else         { a1 = v0; i1 = l;      a2 = v1; i2 = l + 32; }

#pragma unroll
    for (int o = 16; o > 0; o >>= 1) {
        const float b1 = __shfl_xor_sync(0xffffffffu, a1, o);
        const int  bi1 = __shfl_xor_sync(0xffffffffu, i1, o);
        const float b2 = __shfl_xor_sync(0xffffffffu, a2, o);
        const int  bi2 = __shfl_xor_sync(0xffffffffu, i2, o);

        const bool afirst = (a1 > b1) || (a1 == b1 && i1 < bi1);
        float r1, r2; int ri1, ri2;
        if (afirst) {
            r1 = a1; ri1 = i1;
            const bool asecond = (a2 > b1) || (a2 == b1 && i2 < bi1);
            if (asecond) { r2 = a2; ri2 = i2; } else { r2 = b1; ri2 = bi1; }
        } else {
            r1 = b1; ri1 = bi1;
            const bool bsecond = (b2 > a1) || (b2 == a1 && bi2 < i1);
            if (bsecond) { r2 = b2; ri2 = bi2; } else { r2 = a1; ri2 = i1; }
        }
        a1 = r1; i1 = ri1; a2 = r2; i2 = ri2;
    }

    if (l == 0) {
        const float inv = 1.0f / se;
        out[2 * t + 0] = __expf(a1 - m) * inv;
        out[2 * t + 1] = __expf(a2 - m) * inv;
        out[2 * T + 2 * t + 0] = (float)i1;
        out[2 * T + 2 * t + 1] = (float)i2;
    }
}

extern "C" void kernel_launch(void* const* d_in, const int* in_sizes, int n_in,
                              void* d_out, int out_size)
{
    const float* x = (const float*)d_in[0];
    const float* W = (const float*)d_in[1];
    int sx = in_sizes[0];
    if (n_in >= 2 && in_sizes[0] < in_sizes[1]) {
        x = (const float*)d_in[1];
        W = (const float*)d_in[0];
        sx = in_sizes[1];
    }
    const int T = sx / HS;   // 8192

    w_convert<<<(NEXP * HS) / 256, 256>>>(W);
    router_gemm_mma<<<dim3(T / TM, NSPLIT), THREADS>>>(x);
    router_reduce<<<(T + 7) / 8, 256>>>((float*)d_out, T);
}

// round 14
// speedup vs baseline: 1.6451x; 1.6451x over previous
#include <cuda_runtime.h>
#include <math.h>
#include <stdint.h>

// TopKTokenChoiceRouter: logits = x(8192,4096) @ W(64,4096)^T ; softmax ; top-2.
// Output: [weights (T,2) fp32][indices (T,2) as fp32].
// mma.sync m16n8k8 tf32, 3-product tf32 emulation of fp32 (hi*hi + hi*lo + lo*hi).
// tf32 conversion via integer RNE rounding (cvt.*.tf32 ICEs this ptxas).
// Register-lean loop: no unroll, one-step register double-buffer for B fragments.

#define HS      4096
#define NEXP    64
#define TM      128            // tokens per CTA
#define NSPLIT  2
#define KPS     (HS / NSPLIT)  // 2048
#define NK8     (KPS / 8)      // 256 k8-steps per CTA
#define THREADS 256
#define TTOT    8192
#define GK8     (HS / 8)       // 512 global k8 steps

// W fragment scratch: [k8g][ntile(8)][reg(2)][lane(32)] of float2{hi,lo} = 2 MB
__device__ float2 g_wfrag[GK8 * 8 * 2 * 32];
__device__ float  g_partial[NSPLIT * TTOT * NEXP];     // 4 MB

// fp32 -> tf32 by integer RNE rounding to 10 mantissa bits. Low 13 bits zeroed,
// so hi is exactly representable and lo = v - hi is exact in fp32.
__device__ __forceinline__ uint32_t f32_to_tf32(float x) {
    uint32_t b = __float_as_uint(x);
    b += 0xFFFu + ((b >> 13) & 1u);
    return b & 0xFFFFE000u;
}

__device__ __forceinline__ void mma_tf32(float* c, const uint32_t* a, const uint32_t* b) {
    asm volatile(
        "mma.sync.aligned.m16n8k8.row.col.f32.tf32.tf32.f32 "
        "{%0,%1,%2,%3}, {%4,%5,%6,%7}, {%8,%9}, {%0,%1,%2,%3};"
        : "+f"(c[0]), "+f"(c[1]), "+f"(c[2]), "+f"(c[3])
        : "r"(a[0]), "r"(a[1]), "r"(a[2]), "r"(a[3]), "r"(b[0]), "r"(b[1]));
}

__device__ __forceinline__ void load_B(const float2* __restrict__ wf, int k8,
                                       uint32_t bh[4][2], uint32_t bl[4][2]) {
#pragma unroll
    for (int nt = 0; nt < 4; nt++)
#pragma unroll
        for (int reg = 0; reg < 2; reg++) {
            const float2 f = wf[((long)k8 * 8 + nt) * 64 + reg * 32];
            bh[nt][reg] = __float_as_uint(f.x);
            bl[nt][reg] = __float_as_uint(f.y);
        }
}

// ---------------- W pre-convert: fp32 -> tf32 hi/lo, fragment-ordered ----------------
__global__ void w_convert(const float* __restrict__ W)
{
    const int idx = blockIdx.x * 256 + threadIdx.x;   // 0 .. 64*4096-1
    const int n = idx >> 12;          // expert 0..63
    const int k = idx & 4095;
    const float v = W[idx];
    const uint32_t hb = f32_to_tf32(v);
    const float    hf = __uint_as_float(hb);
    const uint32_t lb = f32_to_tf32(v - hf);

    const int k8g = k >> 3;
    const int kin = k & 7;
    const int t   = kin & 3;
    const int reg = kin >> 2;
    const int nt  = n >> 3;
    const int lane = (n & 7) * 4 + t;   // B frag: col(n%8) = lane>>2, k%4 = lane&3
    g_wfrag[((k8g * 8 + nt) * 2 + reg) * 32 + lane] =
        make_float2(__uint_as_float(hb), __uint_as_float(lb));
}

// ---------------- GEMM partial kernel (mma.sync tf32) ----------------
__global__ __launch_bounds__(THREADS)
void router_gemm_mma(const float* __restrict__ x)
{
    const int tid  = threadIdx.x;
    const int w    = tid >> 5;          // warp 0..7
    const int lane = tid & 31;
    const int g    = lane >> 2;         // group 0..7
    const int t    = lane & 3;          // thread-in-group 0..3

    const int tok0  = blockIdx.x * TM;
    const int split = blockIdx.y;
    const int k8b   = split * (KPS / 8);   // global k8 base

    const int R0  = tok0 + (w >> 1) * 32;  // warp's first token row (M=32)
    const int ntb = (w & 1) * 4;           // warp's first n-tile (N=32)

    // A row pointers: mt in {0,1}, rows R0+mt*16+g and +8
    const float* xr[2][2];
#pragma unroll
    for (int mt = 0; mt < 2; mt++) {
        xr[mt][0] = x + (long)(R0 + mt * 16 + g) * HS + split * KPS + t;
        xr[mt][1] = xr[mt][0] + 8 * HS;
    }

    const float2* wf = g_wfrag + (long)(k8b * 8 + ntb) * 2 * 32 + lane;

    float acc[2][4][4];
#pragma unroll
    for (int mt = 0; mt < 2; mt++)
#pragma unroll
        for (int nt = 0; nt < 4; nt++)
#pragma unroll
            for (int c = 0; c < 4; c++) acc[mt][nt][c] = 0.0f;

    // B double-buffer in registers
    uint32_t bh[4][2], bl[4][2];
    load_B(wf, 0, bh, bl);

#pragma unroll 1
    for (int k8 = 0; k8 < NK8; k8++) {
        const int ko = k8 * 8;

        // prefetch next k8's B fragments (L2-resident; latency covered by mma chain)
        uint32_t nh[4][2], nl[4][2];
        if (k8 + 1 < NK8) load_B(wf, k8 + 1, nh, nl);

        // A loads for both m-tiles first (independent LDGs, overlap with B latency)
        float av[2][4];
#pragma unroll
        for (int mt = 0; mt < 2; mt++) {
            av[mt][0] = xr[mt][0][ko];       // (g,   t)
            av[mt][1] = xr[mt][1][ko];       // (g+8, t)
            av[mt][2] = xr[mt][0][ko + 4];   // (g,   t+4)
            av[mt][3] = xr[mt][1][ko + 4];   // (g+8, t+4)
        }

#pragma unroll
        for (int mt = 0; mt < 2; mt++) {
            uint32_t ah[4], al[4];
#pragma unroll
            for (int i = 0; i < 4; i++) {
                ah[i] = f32_to_tf32(av[mt][i]);
                al[i] = f32_to_tf32(av[mt][i] - __uint_as_float(ah[i]));
            }
#pragma unroll
            for (int nt = 0; nt < 4; nt++) {
                mma_tf32(acc[mt][nt], ah, bh[nt]);
                mma_tf32(acc[mt][nt], ah, bl[nt]);
                mma_tf32(acc[mt][nt], al, bh[nt]);
            }
        }

        // rotate double buffer (register renaming, no data movement in SASS)
#pragma unroll
        for (int nt = 0; nt < 4; nt++)
#pragma unroll
            for (int reg = 0; reg < 2; reg++) {
                bh[nt][reg] = nh[nt][reg];
                bl[nt][reg] = nl[nt][reg];
            }
    }

    // ---- store partials: c0,c1 -> (row, 2t..2t+1), c2,c3 -> (row+8, ...) ----
    float* pb = g_partial + (long)split * TTOT * NEXP;
#pragma unroll
    for (int mt = 0; mt < 2; mt++) {
#pragma unroll
        for (int h = 0; h < 2; h++) {
            const int row = R0 + mt * 16 + g + 8 * h;
            float* dst = pb + (long)row * NEXP;
#pragma unroll
            for (int nt = 0; nt < 4; nt++)
                *(float2*)&dst[(ntb + nt) * 8 + 2 * t] =
                    make_float2(acc[mt][nt][2 * h], acc[mt][nt][2 * h + 1]);
        }
    }
}

// ---------------- reduce + softmax + top-2 ----------------
__global__ __launch_bounds__(256)
void router_reduce(float* __restrict__ out, int T)
{
    const int wid = threadIdx.x >> 5;
    const int l   = threadIdx.x & 31;
    const int t   = blockIdx.x * 8 + wid;
    if (t >= T) return;

    const float* p = g_partial + (long)t * NEXP + l;
    float v0 = 0.0f, v1 = 0.0f;
#pragma unroll
    for (int s = 0; s < NSPLIT; s++) {
        v0 += p[(long)s * TTOT * NEXP];
        v1 += p[(long)s * TTOT * NEXP + 32];
    }

    float m = fmaxf(v0, v1);
#pragma unroll
    for (int o = 16; o > 0; o >>= 1)
        m = fmaxf(m, __shfl_xor_sync(0xffffffffu, m, o));

    float se = __expf(v0 - m) + __expf(v1 - m);
#pragma unroll
    for (int o = 16; o > 0; o >>= 1)
        se += __shfl_xor_sync(0xffffffffu, se, o);

    float a1, a2; int i1, i2;
    if (v1 > v0) { a1 = v1; i1 = l + 32; a2 = v0; i2 = l; }
    else         { a1 = v0; i1 = l;      a2 = v1; i2 = l + 32; }

#pragma unroll
    for (int o = 16; o > 0; o >>= 1) {
        const float b1 = __shfl_xor_sync(0xffffffffu, a1, o);
        const int  bi1 = __shfl_xor_sync(0xffffffffu, i1, o);
        const float b2 = __shfl_xor_sync(0xffffffffu, a2, o);
        const int  bi2 = __shfl_xor_sync(0xffffffffu, i2, o);

        const bool afirst = (a1 > b1) || (a1 == b1 && i1 < bi1);
        float r1, r2; int ri1, ri2;
        if (afirst) {
            r1 = a1; ri1 = i1;
            const bool asecond = (a2 > b1) || (a2 == b1 && i2 < bi1);
            if (asecond) { r2 = a2; ri2 = i2; } else { r2 = b1; ri2 = bi1; }
        } else {
            r1 = b1; ri1 = bi1;
            const bool bsecond = (b2 > a1) || (b2 == a1 && bi2 < i1);
            if (bsecond) { r2 = b2; ri2 = bi2; } else { r2 = a1; ri2 = i1; }
        }
        a1 = r1; i1 = ri1; a2 = r2; i2 = ri2;
    }

    if (l == 0) {
        const float inv = 1.0f / se;
        out[2 * t + 0] = __expf(a1 - m) * inv;
        out[2 * t + 1] = __expf(a2 - m) * inv;
        out[2 * T + 2 * t + 0] = (float)i1;
        out[2 * T + 2 * t + 1] = (float)i2;
    }
}

extern "C" void kernel_launch(void* const* d_in, const int* in_sizes, int n_in,
                              void* d_out, int out_size)
{
    const float* x = (const float*)d_in[0];
    const float* W = (const float*)d_in[1];
    int sx = in_sizes[0];
    if (n_in >= 2 && in_sizes[0] < in_sizes[1]) {
        x = (const float*)d_in[1];
        W = (const float*)d_in[0];
        sx = in_sizes[1];
    }
    const int T = sx / HS;   // 8192

    w_convert<<<(NEXP * HS) / 256, 256>>>(W);
    router_gemm_mma<<<dim3(T / TM, NSPLIT), THREADS>>>(x);
    router_reduce<<<(T + 7) / 8, 256>>>((float*)d_out, T);
}

// round 16
// speedup vs baseline: 1.9329x; 1.1750x over previous
#include <cuda_runtime.h>
#include <math.h>
#include <stdint.h>

// TopKTokenChoiceRouter: logits = x(8192,4096) @ W(64,4096)^T ; softmax ; top-2.
// Output: [weights (T,2) fp32][indices (T,2) as fp32].
// mma.sync m16n8k8 tf32, 3-product tf32 emulation of fp32 (hi*hi + hi*lo + lo*hi).
// tf32 conversion via integer RNE rounding (cvt.*.tf32 ICEs this ptxas).
// Latency fixes: split-K x4 (2 CTAs/SM) + distance-1 register prefetch for A and B.

#define HS      4096
#define NEXP    64
#define TM      128            // tokens per CTA
#define NSPLIT  4
#define KPS     (HS / NSPLIT)  // 1024
#define NK8     (KPS / 8)      // 128 k8-steps per CTA
#define THREADS 256
#define TTOT    8192
#define GK8     (HS / 8)       // 512 global k8 steps

// W fragment scratch: [k8g][ntile(8)][reg(2)][lane(32)] of float2{hi,lo} = 2 MB
__device__ float2 g_wfrag[GK8 * 8 * 2 * 32];
__device__ float  g_partial[NSPLIT * TTOT * NEXP];     // 8 MB

// fp32 -> tf32 by integer RNE rounding to 10 mantissa bits. Low 13 bits zeroed,
// so hi is exactly representable and lo = v - hi is exact in fp32.
__device__ __forceinline__ uint32_t f32_to_tf32(float x) {
    uint32_t b = __float_as_uint(x);
    b += 0xFFFu + ((b >> 13) & 1u);
    return b & 0xFFFFE000u;
}

__device__ __forceinline__ void mma_tf32(float* c, const uint32_t* a, const uint32_t* b) {
    asm volatile(
        "mma.sync.aligned.m16n8k8.row.col.f32.tf32.tf32.f32 "
        "{%0,%1,%2,%3}, {%4,%5,%6,%7}, {%8,%9}, {%0,%1,%2,%3};"
        : "+f"(c[0]), "+f"(c[1]), "+f"(c[2]), "+f"(c[3])
        : "r"(a[0]), "r"(a[1]), "r"(a[2]), "r"(a[3]), "r"(b[0]), "r"(b[1]));
}

__device__ __forceinline__ void load_B(const float2* __restrict__ wf, int k8,
                                       uint32_t bh[4][2], uint32_t bl[4][2]) {
#pragma unroll
    for (int nt = 0; nt < 4; nt++)
#pragma unroll
        for (int reg = 0; reg < 2; reg++) {
            const float2 f = wf[((long)k8 * 8 + nt) * 64 + reg * 32];
            bh[nt][reg] = __float_as_uint(f.x);
            bl[nt][reg] = __float_as_uint(f.y);
        }
}

// ---------------- W pre-convert: fp32 -> tf32 hi/lo, fragment-ordered ----------------
__global__ void w_convert(const float* __restrict__ W)
{
    const int idx = blockIdx.x * 256 + threadIdx.x;   // 0 .. 64*4096-1
    const int n = idx >> 12;          // expert 0..63
    const int k = idx & 4095;
    const float v = W[idx];
    const uint32_t hb = f32_to_tf32(v);
    const float    hf = __uint_as_float(hb);
    const uint32_t lb = f32_to_tf32(v - hf);

    const int k8g = k >> 3;
    const int kin = k & 7;
    const int t   = kin & 3;
    const int reg = kin >> 2;
    const int nt  = n >> 3;
    const int lane = (n & 7) * 4 + t;   // B frag: col(n%8) = lane>>2, k%4 = lane&3
    g_wfrag[((k8g * 8 + nt) * 2 + reg) * 32 + lane] =
        make_float2(__uint_as_float(hb), __uint_as_float(lb));
}

// ---------------- GEMM partial kernel (mma.sync tf32) ----------------
__global__ __launch_bounds__(THREADS, 2)
void router_gemm_mma(const float* __restrict__ x)
{
    const int tid  = threadIdx.x;
    const int w    = tid >> 5;          // warp 0..7
    const int lane = tid & 31;
    const int g    = lane >> 2;         // group 0..7
    const int t    = lane & 3;          // thread-in-group 0..3

    const int tok0  = blockIdx.x * TM;
    const int split = blockIdx.y;
    const int k8b   = split * (KPS / 8);   // global k8 base

    const int R0  = tok0 + (w >> 1) * 32;  // warp's first token row (M=32)
    const int ntb = (w & 1) * 4;           // warp's first n-tile (N=32)

    // A row pointers: mt in {0,1}, rows R0+mt*16+g and +8
    const float* xr[2][2];
#pragma unroll
    for (int mt = 0; mt < 2; mt++) {
        xr[mt][0] = x + (long)(R0 + mt * 16 + g) * HS + split * KPS + t;
        xr[mt][1] = xr[mt][0] + 8 * HS;
    }

    const float2* wf = g_wfrag + (long)(k8b * 8 + ntb) * 2 * 32 + lane;

    float acc[2][4][4];
#pragma unroll
    for (int mt = 0; mt < 2; mt++)
#pragma unroll
        for (int nt = 0; nt < 4; nt++)
#pragma unroll
            for (int c = 0; c < 4; c++) acc[mt][nt][c] = 0.0f;

    // B and A double-buffers in registers (distance-1 prefetch)
    uint32_t bh[4][2], bl[4][2];
    load_B(wf, 0, bh, bl);

    float av[2][2][4];                 // [buf][mt][i]
#pragma unroll
    for (int mt = 0; mt < 2; mt++) {
        av[0][mt][0] = xr[mt][0][0];
        av[0][mt][1] = xr[mt][1][0];
        av[0][mt][2] = xr[mt][0][4];
        av[0][mt][3] = xr[mt][1][4];
    }

#pragma unroll 1
    for (int k8 = 0; k8 < NK8; k8++) {
        const int cur = k8 & 1;
        const int nxt = cur ^ 1;

        // prefetch next iteration's A (8 independent DRAM/L1 loads) and B (L2)
        uint32_t nh[4][2], nl[4][2];
        if (k8 + 1 < NK8) {
            const int ko = (k8 + 1) * 8;
#pragma unroll
            for (int mt = 0; mt < 2; mt++) {
                av[nxt][mt][0] = xr[mt][0][ko];       // (g,   t)
                av[nxt][mt][1] = xr[mt][1][ko];       // (g+8, t)
                av[nxt][mt][2] = xr[mt][0][ko + 4];   // (g,   t+4)
                av[nxt][mt][3] = xr[mt][1][ko + 4];   // (g+8, t+4)
            }
            load_B(wf, k8 + 1, nh, nl);
        }

#pragma unroll
        for (int mt = 0; mt < 2; mt++) {
            uint32_t ah[4], al[4];
#pragma unroll
            for (int i = 0; i < 4; i++) {
                ah[i] = f32_to_tf32(av[cur][mt][i]);
                al[i] = f32_to_tf32(av[cur][mt][i] - __uint_as_float(ah[i]));
            }
#pragma unroll
            for (int nt = 0; nt < 4; nt++) {
                mma_tf32(acc[mt][nt], ah, bh[nt]);
                mma_tf32(acc[mt][nt], ah, bl[nt]);
                mma_tf32(acc[mt][nt], al, bh[nt]);
            }
        }

        // rotate B double buffer
#pragma unroll
        for (int nt = 0; nt < 4; nt++)
#pragma unroll
            for (int reg = 0; reg < 2; reg++) {
                bh[nt][reg] = nh[nt][reg];
                bl[nt][reg] = nl[nt][reg];
            }
    }

    // ---- store partials: c0,c1 -> (row, 2t..2t+1), c2,c3 -> (row+8, ...) ----
    float* pb = g_partial + (long)split * TTOT * NEXP;
#pragma unroll
    for (int mt = 0; mt < 2; mt++) {
#pragma unroll
        for (int h = 0; h < 2; h++) {
            const int row = R0 + mt * 16 + g + 8 * h;
            float* dst = pb + (long)row * NEXP;
#pragma unroll
            for (int nt = 0; nt < 4; nt++)
                *(float2*)&dst[(ntb + nt) * 8 + 2 * t] =
                    make_float2(acc[mt][nt][2 * h], acc[mt][nt][2 * h + 1]);
        }
    }
}

// ---------------- reduce + softmax + top-2 ----------------
__global__ __launch_bounds__(256)
void router_reduce(float* __restrict__ out, int T)
{
    const int wid = threadIdx.x >> 5;
    const int l   = threadIdx.x & 31;
    const int t   = blockIdx.x * 8 + wid;
    if (t >= T) return;

    const float* p = g_partial + (long)t * NEXP + l;
    float v0 = 0.0f, v1 = 0.0f;
#pragma unroll
    for (int s = 0; s < NSPLIT; s++) {
        v0 += p[(long)s * TTOT * NEXP];
        v1 += p[(long)s * TTOT * NEXP + 32];
    }

    float m = fmaxf(v0, v1);
#pragma unroll
    for (int o = 16; o > 0; o >>= 1)
        m = fmaxf(m, __shfl_xor_sync(0xffffffffu, m, o));

    float se = __expf(v0 - m) + __expf(v1 - m);
#pragma unroll
    for (int o = 16; o > 0; o >>= 1)
        se += __shfl_xor_sync(0xffffffffu, se, o);

    float a1, a2; int i1, i2;
    if (v1 > v0) { a1 = v1; i1 = l + 32; a2 = v0; i2 = l; }
    else         { a1 = v0; i1 = l;      a2 = v1; i2 = l + 32; }

#pragma unroll
    for (int o = 16; o > 0; o >>= 1) {
        const float b1 = __shfl_xor_sync(0xffffffffu, a1, o);
        const int  bi1 = __shfl_xor_sync(0xffffffffu, i1, o);
        const float b2 = __shfl_xor_sync(0xffffffffu, a2, o);
        const int  bi2 = __shfl_xor_sync(0xffffffffu, i2, o);

        const bool afirst = (a1 > b1) || (a1 == b1 && i1 < bi1);
        float r1, r2; int ri1, ri2;
        if (afirst) {
            r1 = a1; ri1 = i1;
            const bool asecond = (a2 > b1) || (a2 == b1 && i2 < bi1);
            if (asecond) { r2 = a2; ri2 = i2; } else { r2 = b1; ri2 = bi1; }
        } else {
            r1 = b1; ri1 = bi1;
            const bool bsecond = (b2 > a1) || (b2 == a1 && bi2 < i1);
            if (bsecond) { r2 = b2; ri2 = bi2; } else { r2 = a1; ri2 = i1; }
        }
        a1 = r1; i1 = ri1; a2 = r2; i2 = ri2;
    }

    if (l == 0) {
        const float inv = 1.0f / se;
        out[2 * t + 0] = __expf(a1 - m) * inv;
        out[2 * t + 1] = __expf(a2 - m) * inv;
        out[2 * T + 2 * t + 0] = (float)i1;
        out[2 * T + 2 * t + 1] = (float)i2;
    }
}

extern "C" void kernel_launch(void* const* d_in, const int* in_sizes, int n_in,
                              void* d_out, int out_size)
{
    const float* x = (const float*)d_in[0];
    const float* W = (const float*)d_in[1];
    int sx = in_sizes[0];
    if (n_in >= 2 && in_sizes[0] < in_sizes[1]) {
        x = (const float*)d_in[1];
        W = (const float*)d_in[0];
        sx = in_sizes[1];
    }
    const int T = sx / HS;   // 8192

    w_convert<<<(NEXP * HS) / 256, 256>>>(W);
    router_gemm_mma<<<dim3(T / TM, NSPLIT), THREADS>>>(x);
    router_reduce<<<(T + 7) / 8, 256>>>((float*)d_out, T);
}